// round 4
// baseline (speedup 1.0000x reference)
#include <cuda_runtime.h>
#include <cuda_bf16.h>
#include <cstdint>

// Problem constants
#define NE 8
#define NH 1024
#define NI 2048
#define NT 1024
#define NPAIR (NT * 2)
#define N1 (2 * NI)

// ---------------------------------------------------------------------------
// Scratch
// ---------------------------------------------------------------------------
__device__ int g_cnt[NE];
__device__ int g_off[NE];
__device__ int g_pair_token[NPAIR];
__device__ float g_pair_w[NPAIR];

__device__ __align__(16) __nv_bfloat16 g_Ahi[NPAIR * NH];
__device__ __align__(16) __nv_bfloat16 g_Alo[NPAIR * NH];
__device__ __align__(16) __nv_bfloat16 g_acthi[NPAIR * NI];
__device__ __align__(16) __nv_bfloat16 g_actlo[NPAIR * NI];

// ---------------------------------------------------------------------------
// Router: top-2 + per-expert compaction (one 1024-thread block)
// ---------------------------------------------------------------------------
__global__ void router_kernel(const float* __restrict__ logits) {
    __shared__ int s_cnt[NE];
    __shared__ int s_cur[NE];
    int t = threadIdx.x;
    if (t < NE) s_cnt[t] = 0;
    __syncthreads();

    float l[NE];
#pragma unroll
    for (int e = 0; e < NE; e++) l[e] = logits[t * NE + e];

    int e0 = 0;
#pragma unroll
    for (int e = 1; e < NE; e++) if (l[e] > l[e0]) e0 = e;
    int e1 = (e0 == 0) ? 1 : 0;
#pragma unroll
    for (int e = 0; e < NE; e++) if (e != e0 && l[e] > l[e1]) e1 = e;

    float w0 = 1.0f / (1.0f + expf(l[e1] - l[e0]));
    float w1 = 1.0f - w0;

    atomicAdd(&s_cnt[e0], 1);
    atomicAdd(&s_cnt[e1], 1);
    __syncthreads();

    if (t == 0) {
        int o = 0;
        for (int e = 0; e < NE; e++) {
            g_off[e] = o;
            s_cur[e] = o;
            g_cnt[e] = s_cnt[e];
            o += s_cnt[e];
        }
    }
    __syncthreads();

    int p0 = atomicAdd(&s_cur[e0], 1);
    int p1 = atomicAdd(&s_cur[e1], 1);
    g_pair_token[p0] = t;  g_pair_w[p0] = w0;
    g_pair_token[p1] = t;  g_pair_w[p1] = w1;
}

// ---------------------------------------------------------------------------
// Gather x rows -> compacted bf16 hi/lo
// ---------------------------------------------------------------------------
__global__ void gather_kernel(const float* __restrict__ x) {
    int p = blockIdx.x;
    int t = g_pair_token[p];
    float4 v = reinterpret_cast<const float4*>(x + (size_t)t * NH)[threadIdx.x];
    int base = p * NH + threadIdx.x * 4;
    float f[4] = {v.x, v.y, v.z, v.w};
#pragma unroll
    for (int j = 0; j < 4; j++) {
        __nv_bfloat16 hi = __float2bfloat16(f[j]);
        g_Ahi[base + j] = hi;
        g_Alo[base + j] = __float2bfloat16(f[j] - __bfloat162float(hi));
    }
}

// ---------------------------------------------------------------------------
// Fused pipelined GEMM
//  PASS 1: (Ahi+Alo)[M,1024] @ w13 tiles (64 glu + 64 lin cols) -> swiglu
//          -> acthi/actlo   (epilogue-fused activation)
//  PASS 2: (acthi+actlo)[M,2048] @ w2 tile (64 cols) -> atomicAdd gated
//          combine (+bias) into out
// ---------------------------------------------------------------------------
#define BM 128
#define BK 32
#define AKP 40   // A smem stride in halfs (80B, 16B-aligned, conflict-free)
#define BKP 40   // B smem stride in floats (160B, 16B-aligned, conflict-free)

__device__ __forceinline__ unsigned su32(const void* p) {
    return (unsigned)__cvta_generic_to_shared(p);
}
__device__ __forceinline__ void cpa16(unsigned dst, const void* src, int sz) {
    asm volatile("cp.async.ca.shared.global [%0], [%1], 16, %2;\n"
                 :: "r"(dst), "l"(src), "r"(sz));
}
__device__ __forceinline__ void mma16816(float* c, const uint32_t* a, const uint32_t* b) {
    asm volatile(
        "mma.sync.aligned.m16n8k16.row.col.f32.bf16.bf16.f32 "
        "{%0,%1,%2,%3}, {%4,%5,%6,%7}, {%8,%9}, {%0,%1,%2,%3};\n"
        : "+f"(c[0]), "+f"(c[1]), "+f"(c[2]), "+f"(c[3])
        : "r"(a[0]), "r"(a[1]), "r"(a[2]), "r"(a[3]), "r"(b[0]), "r"(b[1]));
}
__device__ __forceinline__ uint32_t cvt_bf16x2(float hi, float lo) {
    uint32_t r;
    asm("cvt.rn.bf16x2.f32 %0, %1, %2;" : "=r"(r) : "f"(hi), "f"(lo));
    return r;
}

template <int PASS>
__global__ __launch_bounds__(256, 2) void gemm_fused(
    const float* __restrict__ Bw, const float* __restrict__ bias,
    float* __restrict__ out)
{
    constexpr int K   = (PASS == 1) ? NH : NI;
    constexpr int NBR = (PASS == 1) ? 128 : 64;   // B rows per tile
    constexpr int NIW = NBR / 16;                 // ni per warp (8 or 4)
    constexpr int KT  = K / BK;
    constexpr int ABYTES = BM * AKP * 2;          // 10240 per A matrix
    constexpr int BBYTES = NBR * BKP * 4;
    constexpr int STAGE  = 2 * ABYTES + BBYTES;

    const int e = blockIdx.z;
    const int cntE = g_cnt[e];
    const int m0 = blockIdx.x * BM;
    if (m0 >= cntE) return;
    const int offE = g_off[e];
    const int n0 = blockIdx.y * 64;

    extern __shared__ char smem[];

    const int tid = threadIdx.x;
    const int lane = tid & 31;
    const int warp = tid >> 5;
    const int wm = warp >> 1;
    const int wn = warp & 1;

    const __nv_bfloat16* __restrict__ Ahi = (PASS == 1) ? g_Ahi : g_acthi;
    const __nv_bfloat16* __restrict__ Alo = (PASS == 1) ? g_Alo : g_actlo;

    auto issue = [&](int kt, int s) {
        const int k0 = kt * BK;
        char* st = smem + s * STAGE;
#pragma unroll
        for (int j = 0; j < 2; j++) {
            int cid = tid + j * 256;
            int row = cid >> 2;
            int c16 = cid & 3;
            int vr = m0 + row;
            int sz = (vr < cntE) ? 16 : 0;
            int cr = (vr < cntE) ? vr : (cntE - 1);
            size_t gof = (size_t)(offE + cr) * K + k0;
            cpa16(su32(st + row * 80 + c16 * 16),
                  (const char*)(Ahi + gof) + c16 * 16, sz);
            cpa16(su32(st + ABYTES + row * 80 + c16 * 16),
                  (const char*)(Alo + gof) + c16 * 16, sz);
        }
#pragma unroll
        for (int j = 0; j < NBR / 32; j++) {
            int cid = tid + j * 256;
            int row = cid >> 3;
            int c16 = cid & 7;
            size_t grow;
            if (PASS == 1)
                grow = (size_t)e * N1 + ((row < 64) ? (n0 + row) : (NI + n0 + row - 64));
            else
                grow = (size_t)e * NH + n0 + row;
            cpa16(su32(st + 2 * ABYTES + row * 160 + c16 * 16),
                  (const char*)(Bw + grow * K + k0) + c16 * 16, 16);
        }
        asm volatile("cp.async.commit_group;\n");
    };

    float acc[2][NIW][4];
#pragma unroll
    for (int a = 0; a < 2; a++)
#pragma unroll
        for (int b = 0; b < NIW; b++)
#pragma unroll
            for (int c = 0; c < 4; c++) acc[a][b][c] = 0.0f;

    issue(0, 0);

    for (int kt = 0; kt < KT; kt++) {
        if (kt + 1 < KT) {
            issue(kt + 1, (kt + 1) & 1);
            asm volatile("cp.async.wait_group 1;\n");
        } else {
            asm volatile("cp.async.wait_group 0;\n");
        }
        __syncthreads();

        const int s = kt & 1;
        const __nv_bfloat16* Ahs = (const __nv_bfloat16*)(smem + s * STAGE);
        const __nv_bfloat16* Als = Ahs + BM * AKP;
        const float* Bss = (const float*)(smem + s * STAGE + 2 * ABYTES);

#pragma unroll
        for (int kk = 0; kk < BK; kk += 16) {
            const int c0 = kk + (lane & 3) * 2;
            uint32_t a_hi[2][4], a_lo[2][4], bf[NIW][2];
#pragma unroll
            for (int mi = 0; mi < 2; mi++) {
                int r0 = (wm * 32 + mi * 16 + (lane >> 2)) * AKP;
                a_hi[mi][0] = *(const uint32_t*)(Ahs + r0 + c0);
                a_hi[mi][1] = *(const uint32_t*)(Ahs + r0 + 8 * AKP + c0);
                a_hi[mi][2] = *(const uint32_t*)(Ahs + r0 + c0 + 8);
                a_hi[mi][3] = *(const uint32_t*)(Ahs + r0 + 8 * AKP + c0 + 8);
                a_lo[mi][0] = *(const uint32_t*)(Als + r0 + c0);
                a_lo[mi][1] = *(const uint32_t*)(Als + r0 + 8 * AKP + c0);
                a_lo[mi][2] = *(const uint32_t*)(Als + r0 + c0 + 8);
                a_lo[mi][3] = *(const uint32_t*)(Als + r0 + 8 * AKP + c0 + 8);
            }
#pragma unroll
            for (int ni = 0; ni < NIW; ni++) {
                int br = ((ni >> 2) * 64 + wn * 32 + (ni & 3) * 8 + (lane >> 2)) * BKP;
                float2 v0 = *(const float2*)(Bss + br + c0);
                float2 v1 = *(const float2*)(Bss + br + c0 + 8);
                bf[ni][0] = cvt_bf16x2(v0.y, v0.x);
                bf[ni][1] = cvt_bf16x2(v1.y, v1.x);
            }
#pragma unroll
            for (int mi = 0; mi < 2; mi++)
#pragma unroll
                for (int ni = 0; ni < NIW; ni++) {
                    mma16816(acc[mi][ni], a_hi[mi], bf[ni]);
                    mma16816(acc[mi][ni], a_lo[mi], bf[ni]);
                }
        }
        __syncthreads();
    }

    // ------------------- epilogue -------------------
    if (PASS == 1) {
#pragma unroll
        for (int mi = 0; mi < 2; mi++) {
#pragma unroll
            for (int ni = 0; ni < 4; ni++) {
                int colb = n0 + wn * 32 + ni * 8 + (lane & 3) * 2;
                float bg0 = bias[e * N1 + colb];
                float bg1 = bias[e * N1 + colb + 1];
                float bl0 = bias[e * N1 + NI + colb];
                float bl1 = bias[e * N1 + NI + colb + 1];
#pragma unroll
                for (int h = 0; h < 2; h++) {
                    int rr = m0 + wm * 32 + mi * 16 + (lane >> 2) + h * 8;
                    if (rr < cntE) {
                        int p = offE + rr;
                        float g0 = acc[mi][ni][h * 2 + 0] + bg0;
                        float g1 = acc[mi][ni][h * 2 + 1] + bg1;
                        float l0 = acc[mi][ni + 4][h * 2 + 0] + bl0;
                        float l1 = acc[mi][ni + 4][h * 2 + 1] + bl1;
                        float a0 = g0 * (1.0f / (1.0f + __expf(-1.702f * g0))) * (l0 + 1.0f);
                        float a1 = g1 * (1.0f / (1.0f + __expf(-1.702f * g1))) * (l1 + 1.0f);
                        __nv_bfloat16 h0 = __float2bfloat16(a0);
                        __nv_bfloat16 h1 = __float2bfloat16(a1);
                        __nv_bfloat162 hv; hv.x = h0; hv.y = h1;
                        __nv_bfloat162 lv;
                        lv.x = __float2bfloat16(a0 - __bfloat162float(h0));
                        lv.y = __float2bfloat16(a1 - __bfloat162float(h1));
                        *(__nv_bfloat162*)(g_acthi + (size_t)p * NI + colb) = hv;
                        *(__nv_bfloat162*)(g_actlo + (size_t)p * NI + colb) = lv;
                    }
                }
            }
        }
    } else {
#pragma unroll
        for (int mi = 0; mi < 2; mi++) {
#pragma unroll
            for (int h = 0; h < 2; h++) {
                int rr = m0 + wm * 32 + mi * 16 + (lane >> 2) + h * 8;
                if (rr < cntE) {
                    int p = offE + rr;
                    int t = g_pair_token[p];
                    float gw = g_pair_w[p];
#pragma unroll
                    for (int ni = 0; ni < 4; ni++) {
                        int colb = n0 + wn * 32 + ni * 8 + (lane & 3) * 2;
                        float y0 = acc[mi][ni][h * 2 + 0] + bias[e * NH + colb];
                        float y1 = acc[mi][ni][h * 2 + 1] + bias[e * NH + colb + 1];
                        atomicAdd(&out[(size_t)t * NH + colb], gw * y0);
                        atomicAdd(&out[(size_t)t * NH + colb + 1], gw * y1);
                    }
                }
            }
        }
    }
}

// ---------------------------------------------------------------------------
// Launch
// ---------------------------------------------------------------------------
extern "C" void kernel_launch(void* const* d_in, const int* in_sizes, int n_in,
                              void* d_out, int out_size) {
    const float* x      = (const float*)d_in[0];
    const float* logits = (const float*)d_in[1];
    const float* w13    = (const float*)d_in[2];
    const float* w2     = (const float*)d_in[3];
    const float* b13    = (const float*)d_in[4];
    const float* b2     = (const float*)d_in[5];
    float* out = (float*)d_out;

    constexpr int SMEM1 = 2 * (2 * BM * AKP * 2 + 128 * BKP * 4);  // 81920
    constexpr int SMEM2 = 2 * (2 * BM * AKP * 2 + 64 * BKP * 4);   // 61440
    cudaFuncSetAttribute(gemm_fused<1>, cudaFuncAttributeMaxDynamicSharedMemorySize, SMEM1);
    cudaFuncSetAttribute(gemm_fused<2>, cudaFuncAttributeMaxDynamicSharedMemorySize, SMEM2);

    cudaMemsetAsync(d_out, 0, (size_t)out_size * sizeof(float));
    router_kernel<<<1, NT>>>(logits);
    gather_kernel<<<NPAIR, 256>>>(x);
    gemm_fused<1><<<dim3(16, 32, 8), 256, SMEM1>>>(w13, b13, nullptr);
    gemm_fused<2><<<dim3(16, 16, 8), 256, SMEM2>>>(w2, b2, out);
}

// round 14
// speedup vs baseline: 2.0822x; 2.0822x over previous
#include <cuda_runtime.h>
#include <cuda_fp16.h>
#include <cstdint>

#define NE 8
#define NH 1024
#define NI 2048
#define NT 1024
#define NPAIR (NT * 2)
#define N1 (2 * NI)

// ---------------------------------------------------------------------------
// Scratch
// ---------------------------------------------------------------------------
__device__ int g_cnt[NE];
__device__ int g_off[NE];
__device__ int g_pair_token[NPAIR];
__device__ float g_pair_w[NPAIR];

__device__ __align__(16) __half g_Ah[NPAIR * NH];    // gathered x, fp16
__device__ __align__(16) __half g_act[NPAIR * NI];   // swiglu output, fp16

// ---------------------------------------------------------------------------
// Helpers
// ---------------------------------------------------------------------------
__device__ __forceinline__ uint32_t s2u(const void* p) {
    uint32_t a;
    asm("{ .reg .u64 t; cvta.to.shared.u64 t, %1; cvt.u32.u64 %0, t; }" : "=r"(a) : "l"(p));
    return a;
}
__device__ __forceinline__ void cpa16(uint32_t dst, const void* src, int sz) {
    asm volatile("cp.async.ca.shared.global [%0], [%1], 16, %2;\n" :: "r"(dst), "l"(src), "r"(sz));
}
__device__ __forceinline__ void mma_f16(float* c, const uint32_t* a, const uint32_t* b) {
    asm volatile(
        "mma.sync.aligned.m16n8k16.row.col.f32.f16.f16.f32 "
        "{%0,%1,%2,%3}, {%4,%5,%6,%7}, {%8,%9}, {%0,%1,%2,%3};\n"
        : "+f"(c[0]), "+f"(c[1]), "+f"(c[2]), "+f"(c[3])
        : "r"(a[0]), "r"(a[1]), "r"(a[2]), "r"(a[3]), "r"(b[0]), "r"(b[1]));
}
#define LDSM4(r0, r1, r2, r3, a) \
    asm volatile("ldmatrix.sync.aligned.m8n8.x4.shared.b16 {%0,%1,%2,%3}, [%4];" \
                 : "=r"(r0), "=r"(r1), "=r"(r2), "=r"(r3) : "r"(a))

// ---------------------------------------------------------------------------
// Router: top-2 + per-expert compaction
// ---------------------------------------------------------------------------
__global__ void router_kernel(const float* __restrict__ logits) {
    __shared__ int s_cnt[NE];
    __shared__ int s_cur[NE];
    int t = threadIdx.x;
    if (t < NE) s_cnt[t] = 0;
    __syncthreads();

    float l[NE];
#pragma unroll
    for (int e = 0; e < NE; e++) l[e] = logits[t * NE + e];

    int e0 = 0;
#pragma unroll
    for (int e = 1; e < NE; e++) if (l[e] > l[e0]) e0 = e;
    int e1 = (e0 == 0) ? 1 : 0;
#pragma unroll
    for (int e = 0; e < NE; e++) if (e != e0 && l[e] > l[e1]) e1 = e;

    float w0 = 1.0f / (1.0f + expf(l[e1] - l[e0]));
    float w1 = 1.0f - w0;

    atomicAdd(&s_cnt[e0], 1);
    atomicAdd(&s_cnt[e1], 1);
    __syncthreads();

    if (t == 0) {
        int o = 0;
        for (int e = 0; e < NE; e++) {
            g_off[e] = o;
            s_cur[e] = o;
            g_cnt[e] = s_cnt[e];
            o += s_cnt[e];
        }
    }
    __syncthreads();

    int p0 = atomicAdd(&s_cur[e0], 1);
    int p1 = atomicAdd(&s_cur[e1], 1);
    g_pair_token[p0] = t;  g_pair_w[p0] = w0;
    g_pair_token[p1] = t;  g_pair_w[p1] = w1;
}

// ---------------------------------------------------------------------------
// Gather x rows -> compacted fp16 A
// ---------------------------------------------------------------------------
__global__ void gather_kernel(const float* __restrict__ x) {
    int p = blockIdx.x;
    int t = g_pair_token[p];
    float4 v = reinterpret_cast<const float4*>(x + (size_t)t * NH)[threadIdx.x];
    int base = p * NH + threadIdx.x * 4;
    *reinterpret_cast<__half2*>(g_Ah + base)     = __floats2half2_rn(v.x, v.y);
    *reinterpret_cast<__half2*>(g_Ah + base + 2) = __floats2half2_rn(v.z, v.w);
}

// ---------------------------------------------------------------------------
// Fused HMMA GEMM (fp16 operands, fp32 accum).
//  PASS 1: A[128,1024] @ w13 tiles (64 glu + 64 lin rows) -> swiglu -> g_act
//  PASS 2: act[128,2048] @ w2 tile (64 rows) -> gated atomicAdd combine
// ---------------------------------------------------------------------------
template <int PASS>
__global__ __launch_bounds__(256, 1) void gemm_hmma(
    const float* __restrict__ Bw, const float* __restrict__ bias,
    float* __restrict__ out)
{
    constexpr int K   = (PASS == 1) ? NH : NI;     // 1024 / 2048
    constexpr int BN  = (PASS == 1) ? 128 : 64;    // B tile rows (block N)
    constexpr int NIW = BN / 16;                   // per-warp n-frags: 8 / 4
    constexpr int KT  = K / 64;                    // 16 / 32
    constexpr int NB4 = BN / 16;                   // float4 B-chunks per thread
    constexpr int AST = 128 * 144;                 // A stage bytes (stride 72 halfs)
    constexpr int BST = BN * 144;
    constexpr int STG = AST + BST;

    const int e = blockIdx.z;
    const int cntE = g_cnt[e];
    const int m0 = blockIdx.x * 128;
    if (m0 >= cntE) return;
    const int offE = g_off[e];
    const int n0 = blockIdx.y * 64;   // pass1: glu-col base; pass2: out-col base

    extern __shared__ __align__(16) char smem[];
    const int tid = threadIdx.x, lane = tid & 31, warp = tid >> 5;
    const int wm = warp >> 1, wn = warp & 1;

    // A source is pass-dependent (R6 bug: was hardcoded to g_Ah)
    const __half* __restrict__ Asrc = (PASS == 1) ? g_Ah : g_act;

    float acc[2][NIW][4] = {};
    float4 breg[NB4];

    auto ldgB = [&](int kt) {
#pragma unroll
        for (int j = 0; j < NB4; j++) {
            int cid = tid + j * 256;
            int row = cid >> 4, c4 = cid & 15;
            int grow;
            if (PASS == 1)
                grow = e * N1 + ((row < 64) ? (n0 + row) : (NI + n0 + row - 64));
            else
                grow = e * NH + n0 + row;
            breg[j] = *reinterpret_cast<const float4*>(Bw + (size_t)grow * K + kt * 64 + c4 * 4);
        }
    };
    auto stsB = [&](int s) {
        char* Bs = smem + s * STG + AST;
#pragma unroll
        for (int j = 0; j < NB4; j++) {
            int cid = tid + j * 256;
            int row = cid >> 4, c4 = cid & 15;
            __half2 h0 = __floats2half2_rn(breg[j].x, breg[j].y);
            __half2 h1 = __floats2half2_rn(breg[j].z, breg[j].w);
            uint2 v;
            v.x = *reinterpret_cast<uint32_t*>(&h0);
            v.y = *reinterpret_cast<uint32_t*>(&h1);
            *reinterpret_cast<uint2*>(Bs + row * 144 + c4 * 8) = v;
        }
    };
    auto issueA = [&](int kt, int s) {
        char* As = smem + s * STG;
#pragma unroll
        for (int j = 0; j < 4; j++) {
            int cid = tid + j * 256;
            int row = cid >> 3, c = cid & 7;
            int vr = m0 + row;
            int sz = (vr < cntE) ? 16 : 0;
            int cr = (vr < cntE) ? vr : (cntE - 1);
            const char* src = (const char*)(Asrc + (size_t)(offE + cr) * K + kt * 64) + c * 16;
            cpa16(s2u(As + row * 144 + c * 16), src, sz);
        }
        asm volatile("cp.async.commit_group;\n" ::: "memory");
    };

    // ldmatrix lane offsets (bytes within region)
    const int a_off = ((wm * 32 + (lane & 15)) * 72 + ((lane >> 4) << 3)) * 2;
    int b_off[NIW / 2];
#pragma unroll
    for (int pp = 0; pp < NIW / 2; pp++) {
        int ni = pp * 2 + (lane >> 4);
        int bc = (PASS == 1) ? ((ni & 3) * 8 + wn * 32 + (ni >> 2) * 64)
                             : (wn * 32 + ni * 8);
        b_off[pp] = ((bc + (lane & 7)) * 72 + (((lane >> 3) & 1) << 3)) * 2;
    }

    issueA(0, 0);
    ldgB(0);

    for (int kt = 0; kt < KT; kt++) {
        const int s = kt & 1;
        stsB(s);
        if (kt + 1 < KT) {
            issueA(kt + 1, s ^ 1);
            asm volatile("cp.async.wait_group 1;\n" ::: "memory");
        } else {
            asm volatile("cp.async.wait_group 0;\n" ::: "memory");
        }
        __syncthreads();
        if (kt + 1 < KT) ldgB(kt + 1);

        const uint32_t Ab = s2u(smem + s * STG);
        const uint32_t Bb = Ab + AST;
#pragma unroll
        for (int kk = 0; kk < 64; kk += 16) {
            uint32_t af[2][4];
#pragma unroll
            for (int mi = 0; mi < 2; mi++)
                LDSM4(af[mi][0], af[mi][1], af[mi][2], af[mi][3],
                      Ab + a_off + mi * 2304 + kk * 2);
            uint32_t bf[NIW][2];
#pragma unroll
            for (int pp = 0; pp < NIW / 2; pp++)
                LDSM4(bf[2 * pp][0], bf[2 * pp][1], bf[2 * pp + 1][0], bf[2 * pp + 1][1],
                      Bb + b_off[pp] + kk * 2);
#pragma unroll
            for (int mi = 0; mi < 2; mi++)
#pragma unroll
                for (int ni = 0; ni < NIW; ni++)
                    mma_f16(acc[mi][ni], af[mi], bf[ni]);
        }
        __syncthreads();
    }

    // ------------------- epilogue -------------------
    if (PASS == 1) {
#pragma unroll
        for (int mi = 0; mi < 2; mi++) {
#pragma unroll
            for (int ni = 0; ni < 4; ni++) {
                int cg = wn * 32 + ni * 8 + 2 * (lane & 3);
                float bg0 = bias[e * N1 + n0 + cg];
                float bg1 = bias[e * N1 + n0 + cg + 1];
                float bl0 = bias[e * N1 + NI + n0 + cg];
                float bl1 = bias[e * N1 + NI + n0 + cg + 1];
#pragma unroll
                for (int h = 0; h < 2; h++) {
                    int rr = m0 + wm * 32 + mi * 16 + (lane >> 2) + h * 8;
                    if (rr < cntE) {
                        int p = offE + rr;
                        float g0 = acc[mi][ni][2 * h + 0] + bg0;
                        float g1 = acc[mi][ni][2 * h + 1] + bg1;
                        float l0 = acc[mi][ni + 4][2 * h + 0] + bl0;
                        float l1 = acc[mi][ni + 4][2 * h + 1] + bl1;
                        float a0 = g0 * (1.0f / (1.0f + __expf(-1.702f * g0))) * (l0 + 1.0f);
                        float a1 = g1 * (1.0f / (1.0f + __expf(-1.702f * g1))) * (l1 + 1.0f);
                        *reinterpret_cast<__half2*>(g_act + (size_t)p * NI + n0 + cg) =
                            __floats2half2_rn(a0, a1);
                    }
                }
            }
        }
    } else {
#pragma unroll
        for (int mi = 0; mi < 2; mi++) {
#pragma unroll
            for (int h = 0; h < 2; h++) {
                int rr = m0 + wm * 32 + mi * 16 + (lane >> 2) + h * 8;
                if (rr < cntE) {
                    int p = offE + rr;
                    int t = g_pair_token[p];
                    float gw = g_pair_w[p];
#pragma unroll
                    for (int ni = 0; ni < 4; ni++) {
                        int col = n0 + wn * 32 + ni * 8 + 2 * (lane & 3);
                        float y0 = acc[mi][ni][2 * h + 0] + bias[e * NH + col];
                        float y1 = acc[mi][ni][2 * h + 1] + bias[e * NH + col + 1];
                        atomicAdd(&out[(size_t)t * NH + col], gw * y0);
                        atomicAdd(&out[(size_t)t * NH + col + 1], gw * y1);
                    }
                }
            }
        }
    }
}

// ---------------------------------------------------------------------------
// Launch
// ---------------------------------------------------------------------------
extern "C" void kernel_launch(void* const* d_in, const int* in_sizes, int n_in,
                              void* d_out, int out_size) {
    const float* x      = (const float*)d_in[0];
    const float* logits = (const float*)d_in[1];
    const float* w13    = (const float*)d_in[2];
    const float* w2     = (const float*)d_in[3];
    const float* b13    = (const float*)d_in[4];
    const float* b2     = (const float*)d_in[5];
    float* out = (float*)d_out;

    constexpr int SMEM1 = 2 * (128 * 144 + 128 * 144);  // 73728
    constexpr int SMEM2 = 2 * (128 * 144 + 64 * 144);   // 55296
    cudaFuncSetAttribute(gemm_hmma<1>, cudaFuncAttributeMaxDynamicSharedMemorySize, SMEM1);
    cudaFuncSetAttribute(gemm_hmma<2>, cudaFuncAttributeMaxDynamicSharedMemorySize, SMEM2);

    cudaMemsetAsync(d_out, 0, (size_t)out_size * sizeof(float));
    router_kernel<<<1, NT>>>(logits);
    gather_kernel<<<NPAIR, 256>>>(x);
    gemm_hmma<1><<<dim3(16, 32, 8), 256, SMEM1>>>(w13, b13, nullptr);
    gemm_hmma<2><<<dim3(16, 16, 8), 256, SMEM2>>>(w2, b2, out);
}